// round 2
// baseline (speedup 1.0000x reference)
#include <cuda_runtime.h>
#include <cstdint>

#define Bz 64
#define Sz 512
#define Hz 1024
#define Tz 17
#define ROWS (Bz * Sz)   // 32768

// ---------------------------------------------------------------------------
// Kernel 1: feats[r][t] = dot(x[r,:], W[t,:]) + b[t]
// Block: 256 threads (8 warps). Warp handles 16 rows: lane l -> row pair
// (2*(l/4), +1), sub = l%4 covers h-offsets sub*4..sub*4+3 within each 16-h
// step. W staged through static shared in two 512-h halves (34KB) so x is
// read exactly once and static smem stays < 48KB.
// ---------------------------------------------------------------------------
__global__ __launch_bounds__(256) void crf_gemm_kernel(
    const float* __restrict__ x, const float* __restrict__ W,
    const float* __restrict__ bias, float* __restrict__ feats) {
  __shared__ float Wsh[Tz * 512];  // 34816 B

  const int tid = threadIdx.x;
  const int warp = tid >> 5;
  const int lane = tid & 31;
  const int group = lane >> 2;  // 8 row-pair groups per warp
  const int sub = lane & 3;     // 4 lanes per row pair

  const int rowbase = blockIdx.x * 128 + warp * 16 + group * 2;
  const float* x0 = x + (size_t)rowbase * Hz;
  const float* x1 = x0 + Hz;

  float acc0[Tz], acc1[Tz];
#pragma unroll
  for (int t = 0; t < Tz; t++) { acc0[t] = 0.f; acc1[t] = 0.f; }

  for (int half = 0; half < 2; half++) {
    __syncthreads();  // previous readers done before overwriting Wsh
    // Wsh[t*512 + hh] = W[t*1024 + half*512 + hh]
    for (int i = tid * 4; i < Tz * 512; i += 1024) {
      int t = i >> 9;
      int hh = i & 511;
      *(float4*)&Wsh[i] = *(const float4*)&W[t * Hz + half * 512 + hh];
    }
    __syncthreads();

    const float* xh0 = x0 + half * 512;
    const float* xh1 = x1 + half * 512;
#pragma unroll 2
    for (int h0 = 0; h0 < 512; h0 += 16) {
      const int h = h0 + sub * 4;
      const float4 xa = *(const float4*)(xh0 + h);
      const float4 xb = *(const float4*)(xh1 + h);
#pragma unroll
      for (int t = 0; t < Tz; t++) {
        const float4 wv = *(const float4*)&Wsh[t * 512 + h];
        acc0[t] += xa.x * wv.x + xa.y * wv.y + xa.z * wv.z + xa.w * wv.w;
        acc1[t] += xb.x * wv.x + xb.y * wv.y + xb.z * wv.z + xb.w * wv.w;
      }
    }
  }

  // Reduce across the 4 sub-lanes of each row pair.
#pragma unroll
  for (int t = 0; t < Tz; t++) {
    acc0[t] += __shfl_xor_sync(0xffffffffu, acc0[t], 1);
    acc0[t] += __shfl_xor_sync(0xffffffffu, acc0[t], 2);
    acc1[t] += __shfl_xor_sync(0xffffffffu, acc1[t], 1);
    acc1[t] += __shfl_xor_sync(0xffffffffu, acc1[t], 2);
  }
  if (sub == 0) {
#pragma unroll
    for (int t = 0; t < Tz; t++) {
      feats[(size_t)rowbase * Tz + t] = acc0[t] + bias[t];
      feats[(size_t)(rowbase + 1) * Tz + t] = acc1[t] + bias[t];
    }
  }
}

// ---------------------------------------------------------------------------
// Kernel 2: Viterbi per batch. 64 blocks x 128 threads; warp 0 runs the
// recurrence (lane t owns tag t; score exchanged via shfl). Only steps
// s = 1..nwords-1 are executed: masked steps are identity in the reference
// (score unchanged, bp = id), and padded_tags zeroes s >= nwords anyway.
// ---------------------------------------------------------------------------
__device__ __forceinline__ float max17(const float* c) {
  float a = fmaxf(fmaxf(fmaxf(c[0], c[1]), fmaxf(c[2], c[3])),
                  fmaxf(fmaxf(c[4], c[5]), fmaxf(c[6], c[7])));
  float b = fmaxf(fmaxf(fmaxf(c[8], c[9]), fmaxf(c[10], c[11])),
                  fmaxf(fmaxf(c[12], c[13]), fmaxf(c[14], c[15])));
  return fmaxf(fmaxf(a, b), c[16]);
}

__device__ __forceinline__ int argfirst17(const float* c, float m) {
  unsigned eq = 0;
#pragma unroll
  for (int j = 0; j < Tz; j++) eq |= (c[j] == m) ? (1u << j) : 0u;
  return __ffs(eq) - 1;  // first (smallest j) maximum, like jnp.argmax
}

__global__ __launch_bounds__(128) void crf_viterbi_kernel(
    const float* __restrict__ feats, const float* __restrict__ trans,
    const float* __restrict__ start_t, const float* __restrict__ end_t,
    const int* __restrict__ nwords, float* __restrict__ tags_out) {
  __shared__ float fsh[Sz * Tz];           // 34816 B
  __shared__ unsigned char bp_sh[Sz * Tz]; // 8704 B

  const int b = blockIdx.x;
  const int tid = threadIdx.x;
  const float* fb = feats + (size_t)b * Sz * Tz;

  // Stage this batch's feats into shared (8704 floats, float4 coalesced).
  for (int i = tid * 4; i < Sz * Tz; i += 512)
    *(float4*)&fsh[i] = *(const float4*)&fb[i];

  const int nw = nwords[b];
  __syncthreads();

  if (tid < 32) {
    const int t = tid;
    const int tc = (t < Tz) ? t : (Tz - 1);  // lanes >=17 shadow lane 16 (never read)
    float tcol[Tz];
#pragma unroll
    for (int j = 0; j < Tz; j++) tcol[j] = trans[j * Tz + tc];

    float score = start_t[tc] + fsh[tc];

    for (int s = 1; s < nw; s++) {
      float c[Tz];
#pragma unroll
      for (int j = 0; j < Tz; j++)
        c[j] = __shfl_sync(0xffffffffu, score, j) + tcol[j];
      const float m = max17(c);
      const int bp = argfirst17(c, m);
      score = m + fsh[s * Tz + tc];
      if (t < Tz) bp_sh[s * Tz + t] = (unsigned char)bp;
    }

    // final = score + end_trans; first-argmax over t < 17
    const float fin = score + end_t[tc];
    float fc[Tz];
#pragma unroll
    for (int j = 0; j < Tz; j++) fc[j] = __shfl_sync(0xffffffffu, fin, j);
    const float fm = max17(fc);
    const int last_tag = argfirst17(fc, fm);

    if (t == 0) {
      float* out = tags_out + (size_t)b * Sz;
      int tag = last_tag;
      out[nw - 1] = (float)tag;
      for (int s = nw - 1; s >= 1; s--) {
        tag = bp_sh[s * Tz + tag];
        out[s - 1] = (float)tag;
      }
    }
  }

  // Zero the masked tail (disjoint from backtrack writes).
  for (int s = nw + tid; s < Sz; s += blockDim.x)
    tags_out[(size_t)b * Sz + s] = 0.0f;
}

// ---------------------------------------------------------------------------
// Inputs (metadata order): x, W, b, transitions, start_trans, end_trans, nwords
// Output: [padded_tags (64*512) | feats (64*512*17)] as float32.
// ---------------------------------------------------------------------------
extern "C" void kernel_launch(void* const* d_in, const int* in_sizes, int n_in,
                              void* d_out, int out_size) {
  const float* x = (const float*)d_in[0];
  const float* W = (const float*)d_in[1];
  const float* bias = (const float*)d_in[2];
  const float* trans = (const float*)d_in[3];
  const float* start_t = (const float*)d_in[4];
  const float* end_t = (const float*)d_in[5];
  const int* nwords = (const int*)d_in[6];

  float* tags_out = (float*)d_out;
  float* feats = (float*)d_out + (size_t)Bz * Sz;

  crf_gemm_kernel<<<ROWS / 128, 256>>>(x, W, bias, feats);
  crf_viterbi_kernel<<<Bz, 128>>>(feats, trans, start_t, end_t, nwords, tags_out);
}